// round 2
// baseline (speedup 1.0000x reference)
#include <cuda_runtime.h>
#include <math.h>

#define HH 128
#define WW 128
#define SAT_W 129
#define MAX_PATCH 8192

// Scratch (no allocations allowed): patch coords + reciprocal counts.
__device__ int4  g_coords[MAX_PATCH];
__device__ float g_inv[MAX_PATCH];

// ---------------------------------------------------------------------------
// Kernel 1: compute patch coordinates exactly like the reference.
//   n = i * nrois + r   (patch-major, then roi)
//   x0 = round(xmin + ix*wstep), x1 = round(xmin + ix*wstep + wstep), etc.
// round == rintf (round-half-to-even, matches jnp.round).
// Non-contracted float ops to mirror the reference's evaluation order.
// ---------------------------------------------------------------------------
__global__ void coords_kernel(const float* __restrict__ roi,
                              int nrois, int patch_num, int p) {
    int n = blockIdx.x * blockDim.x + threadIdx.x;
    int N = nrois * patch_num;
    if (n >= N) return;

    int i = n / nrois;     // patch index within roi
    int r = n % nrois;     // roi index

    float4 rb = reinterpret_cast<const float4*>(roi)[r];
    float xmin = rb.x, ymin = rb.y, xmax = rb.z, ymax = rb.w;

    float ix = (float)(i % p);
    float iy = (float)(i / p);
    float pf = (float)p;

    float wstep = __fdiv_rn(__fadd_rn(xmax, -xmin), pf);
    float hstep = __fdiv_rn(__fadd_rn(ymax, -ymin), pf);

    float ax = __fadd_rn(xmin, __fmul_rn(ix, wstep));
    float ay = __fadd_rn(ymin, __fmul_rn(iy, hstep));

    int x0 = (int)rintf(ax);
    int y0 = (int)rintf(ay);
    int x1 = (int)rintf(__fadd_rn(ax, wstep));
    int y1 = (int)rintf(__fadd_rn(ay, hstep));

    // Reference divides by the RAW count; masks clamp implicitly.
    float cnt = (float)((y1 - y0) * (x1 - x0));
    g_inv[n] = 1.0f / fmaxf(cnt, 1.0f);

    // Clamp only for safe SAT indexing (no-op for this data distribution).
    x0 = min(max(x0, 0), WW);  x1 = min(max(x1, 0), WW);
    y0 = min(max(y0, 0), HH);  y1 = min(max(y1, 0), HH);
    g_coords[n] = make_int4(x0, y0, x1, y1);
}

// ---------------------------------------------------------------------------
// Kernel 2: one CTA per channel.
//   1) load the 128x128 plane into smem at [y+1][x+1] (row stride 129),
//      zero the first row/column
//   2) in-place row prefix sums (128 threads, one row each; lane addresses
//      stride 129 floats -> conflict-free)
//   3) in-place column prefix sums (128 threads, one column each; stride 1
//      across lanes -> conflict-free)
//   4) answer all N patch queries with 4 LDS each:
//      sum = S[y1][x1] - S[y0][x1] - S[y1][x0] + S[y0][x0]
// ---------------------------------------------------------------------------
__global__ void __launch_bounds__(256) sat_pool_kernel(
    const float* __restrict__ fm, float* __restrict__ out, int C, int N) {
    extern __shared__ float sat[];   // (HH+1) * SAT_W floats = 66564 B

    const int c   = blockIdx.x;
    const int tid = threadIdx.x;

    // --- load plane (float4 LDG, scalar STS into padded layout) ---
    const float4* src =
        reinterpret_cast<const float4*>(fm + (size_t)c * HH * WW);
    #pragma unroll
    for (int j = tid; j < (HH * WW) / 4; j += 256) {
        float4 v = src[j];
        int lin = j * 4;
        int y = lin >> 7;        // /128
        int x = lin & 127;       // %128
        float* d = &sat[(y + 1) * SAT_W + (x + 1)];
        d[0] = v.x; d[1] = v.y; d[2] = v.z; d[3] = v.w;
    }
    if (tid < SAT_W) {
        sat[tid] = 0.0f;             // row 0
        sat[tid * SAT_W] = 0.0f;     // col 0
    }
    __syncthreads();

    // --- row prefix sums ---
    if (tid < HH) {
        float* row = &sat[(tid + 1) * SAT_W];
        float acc = 0.0f;
        #pragma unroll 8
        for (int x = 1; x <= WW; x++) {
            acc += row[x];
            row[x] = acc;
        }
    }
    __syncthreads();

    // --- column prefix sums ---
    if (tid < WW) {
        float* colp = &sat[tid + 1];
        float acc = 0.0f;
        #pragma unroll 8
        for (int y = 1; y <= HH; y++) {
            acc += colp[y * SAT_W];
            colp[y * SAT_W] = acc;
        }
    }
    __syncthreads();

    // --- gather: 4 LDS per patch ---
    for (int n = tid; n < N; n += 256) {
        int4 q = g_coords[n];            // x0, y0, x1, y1
        float s = sat[q.w * SAT_W + q.z]
                - sat[q.y * SAT_W + q.z]
                - sat[q.w * SAT_W + q.x]
                + sat[q.y * SAT_W + q.x];
        out[(size_t)n * C + c] = s * g_inv[n];
    }
}

// ---------------------------------------------------------------------------
extern "C" void kernel_launch(void* const* d_in, const int* in_sizes, int n_in,
                              void* d_out, int out_size) {
    const float* fm  = (const float*)d_in[0];
    const float* roi = (const float*)d_in[1];
    float* out = (float*)d_out;

    int C     = in_sizes[0] / (HH * WW);
    int nrois = in_sizes[1] / 4;
    int N     = out_size / C;
    int patch_num = N / nrois;
    int p = (int)(sqrtf((float)patch_num) + 0.5f);

    coords_kernel<<<(N + 255) / 256, 256>>>(roi, nrois, patch_num, p);

    size_t smem = (size_t)(HH + 1) * SAT_W * sizeof(float);
    cudaFuncSetAttribute(sat_pool_kernel,
                         cudaFuncAttributeMaxDynamicSharedMemorySize,
                         (int)smem);
    sat_pool_kernel<<<C, 256, smem>>>(fm, out, C, N);
}